// round 7
// baseline (speedup 1.0000x reference)
#include <cuda_runtime.h>
#include <math.h>

#define NB 2
#define NV 1300
#define NF 2500
#define IH 128
#define IW 128
#define EPSV 1e-8f
#define NSPLIT 16
#define CHMAX 160   // ceil(2500/16)=157, rounded
#define TAU 1e-4f

// Scratch (allocation-free rule: __device__ globals; zero-initialized at load)
__device__ float  g_vtx[NB][NV][3];             // ndcx, ndcy, viewz
__device__ float  g_vn[NB][NV][3];              // accumulated vertex normals (zeroed by prev replay's tail block)
__device__ float4 g_fd[NB][NF * 4];             // per-face packed raster data
// inverted keys: 0 = empty. key = ~((depthbits<<32)|face). atomicMax == min over (depth,face).
__device__ unsigned long long g_best[NB][IH * IW];
__device__ int g_tilecnt[NB][64];               // per-tile chunk completion counters
__device__ int g_shadecnt;                      // global shade completion counter

__device__ __noinline__ float3 xform(float x, float y, float z) {
    float vz = 2.0f - z;                 // view = verts @ diag(-1,1,-1) + (0,0,2)
    float nx = 12.0f * (-x) / vz;
    float ny = 12.0f * y / vz;
    return make_float3(nx, ny, vz);
}

// Fused prep: vertex transform + face raster data + vertex-normal atomics
// (vn accumulation HERE, with the same grid/mapping as R3's k_face — restores
//  the deterministic ordering that gave rel_err 4.5e-8)
__global__ void k_prep(const float* __restrict__ verts, const int* __restrict__ faces) {
    int idx = blockIdx.x * blockDim.x + threadIdx.x;
    if (idx < NB * NV) {
        int b = idx / NV, v = idx - b * NV;
        float3 t = xform(verts[idx * 3 + 0], verts[idx * 3 + 1], verts[idx * 3 + 2]);
        g_vtx[b][v][0] = t.x;
        g_vtx[b][v][1] = t.y;
        g_vtx[b][v][2] = t.z;
    }
    if (idx < NB * NF) {
        int b = idx / NF, f = idx - b * NF;
        int i0 = faces[f * 3 + 0];
        int i1 = faces[f * 3 + 1];
        int i2 = faces[f * 3 + 2];
        const float* w0 = &verts[(b * NV + i0) * 3];
        const float* w1 = &verts[(b * NV + i1) * 3];
        const float* w2 = &verts[(b * NV + i2) * 3];
        float w0x = w0[0], w0y = w0[1], w0z = w0[2];
        float w1x = w1[0], w1y = w1[1], w1z = w1[2];
        float w2x = w2[0], w2y = w2[1], w2z = w2[2];
        float ax = w1x - w0x, ay = w1y - w0y, az = w1z - w0z;
        float bx = w2x - w0x, by = w2y - w0y, bz = w2z - w0z;
        float fx = ay * bz - az * by;
        float fy = az * bx - ax * bz;
        float fz = ax * by - ay * bx;
        atomicAdd(&g_vn[b][i0][0], fx); atomicAdd(&g_vn[b][i0][1], fy); atomicAdd(&g_vn[b][i0][2], fz);
        atomicAdd(&g_vn[b][i1][0], fx); atomicAdd(&g_vn[b][i1][1], fy); atomicAdd(&g_vn[b][i1][2], fz);
        atomicAdd(&g_vn[b][i2][0], fx); atomicAdd(&g_vn[b][i2][1], fy); atomicAdd(&g_vn[b][i2][2], fz);

        float3 p0 = xform(w0x, w0y, w0z);
        float3 p1 = xform(w1x, w1y, w1z);
        float3 p2 = xform(w2x, w2y, w2z);
        float v0x = p0.x, v0y = p0.y, t0 = p0.z;
        float v1x = p1.x, v1y = p1.y, t1 = p1.z;
        float v2x = p2.x, v2y = p2.y, t2 = p2.z;

        float area = (v1x - v0x) * (v2y - v0y) - (v1y - v0y) * (v2x - v0x);
        float areaS = (fabsf(area) < EPSV) ? EPSV : area;
        float invA  = 1.0f / areaS;
        bool  ok    = fabsf(area) > EPSV;
        float pad = 1e-5f;
        float xmn = fminf(v0x, fminf(v1x, v2x)) - pad;
        float xmx = fmaxf(v0x, fmaxf(v1x, v2x)) + pad;
        float ymn = fminf(v0y, fminf(v1y, v2y)) - pad;
        float ymx = fmaxf(v0y, fmaxf(v1y, v2y)) + pad;
        if (!ok) { xmn = 1e30f; xmx = -1e30f; }   // degenerate: empty bbox
        float minz = fminf(t0, fminf(t1, t2));
        g_fd[b][f * 4 + 0] = make_float4(v0x, v0y, v1x, v1y);
        g_fd[b][f * 4 + 1] = make_float4(v2x, v2y, invA, areaS);
        g_fd[b][f * 4 + 2] = make_float4(1.0f / t0, 1.0f / t1, 1.0f / t2, minz);
        g_fd[b][f * 4 + 3] = make_float4(xmn, xmx, ymn, ymx);
    }
}

// Fused render + last-block-per-tile shade + tail cleanup.
__global__ void __launch_bounds__(256, 6) k_render(const float* __restrict__ verts,
                                                   const int* __restrict__ faces,
                                                   float* __restrict__ out) {
    __shared__ float4 sm[CHMAX * 4];
    __shared__ unsigned short list[CHMAX];
    __shared__ int warpcnt[8];
    __shared__ int warpoff[8];
    __shared__ int nlist;
    __shared__ int sOld;

    int tid = threadIdx.x;
    int b = blockIdx.y;
    int chunk = blockIdx.z;
    int warp = tid >> 5, lane = tid & 31;
    int jx0 = (blockIdx.x & 7) << 4;
    int iy0 = (blockIdx.x >> 3) << 4;
    int j = jx0 + (tid & 15);
    int i = iy0 + (tid >> 4);
    float px = 1.0f - (2.0f * (float)j + 1.0f) * (1.0f / (float)IW);
    float py = 1.0f - (2.0f * (float)i + 1.0f) * (1.0f / (float)IH);
    float tpx_hi = 1.0f - (2.0f * (float)jx0 + 1.0f) * (1.0f / (float)IW);
    float tpx_lo = 1.0f - (2.0f * (float)(jx0 + 15) + 1.0f) * (1.0f / (float)IW);
    float tpy_hi = 1.0f - (2.0f * (float)iy0 + 1.0f) * (1.0f / (float)IH);
    float tpy_lo = 1.0f - (2.0f * (float)(iy0 + 15) + 1.0f) * (1.0f / (float)IH);

    const int CH = (NF + NSPLIT - 1) / NSPLIT;       // 157
    int fbeg = chunk * CH;
    int cnt = min(NF, fbeg + CH) - fbeg;

    const float4* fd = g_fd[b];
    for (int k = tid; k < cnt * 4; k += 256) sm[k] = fd[fbeg * 4 + k];
    if (tid == 0) nlist = 0;
    __syncthreads();

    // Order-preserving compaction: faces whose bbox intersects the tile rect.
    {
        int k = tid;                      // CH=157 <= 256: single pass
        bool keep = false;
        if (k < cnt) {
            float4 bb = sm[k * 4 + 3];
            keep = (bb.x <= tpx_hi) & (bb.y >= tpx_lo) & (bb.z <= tpy_hi) & (bb.w >= tpy_lo);
        }
        unsigned m = __ballot_sync(0xffffffffu, keep);
        if (lane == 0) warpcnt[warp] = __popc(m);
        __syncthreads();
        if (tid == 0) {
            int s = 0;
            #pragma unroll
            for (int w = 0; w < 8; w++) { warpoff[w] = s; s += warpcnt[w]; }
            nlist = s;
        }
        __syncthreads();
        if (keep) {
            int pos = warpoff[warp] + __popc(m & ((1u << lane) - 1u));
            list[pos] = (unsigned short)k;
        }
        __syncthreads();
    }
    int nl = nlist;

    // Snapshot is PRUNE-ONLY (early-z). Local best starts at +inf so every local
    // minimum is committed; atomicMax resolves cross-chunk ties by face index.
    int pix = i * IW + j;
    unsigned long long snap = g_best[b][pix];
    float pruneD = __int_as_float(0x7f800000);
    if (snap != 0ull) pruneD = __uint_as_float((unsigned)((~snap) >> 32));
    float bestd = __int_as_float(0x7f800000);
    float bestS = EPSV;
    int bestf = -1;

    for (int t = 0; t < nl; t++) {
        int k = (int)list[t];
        float4 bb = sm[k * 4 + 3];
        if (px < bb.x || px > bb.y || py < bb.z || py > bb.w) continue;
        float4 q2 = sm[k * 4 + 2];
        float zlim = fminf(pruneD, bestd);
        if (q2.w * (1.0f - 1e-5f) > zlim) continue;   // early-z: final d >= min tz (strict)
        float4 q0 = sm[k * 4 + 0];
        float4 q1 = sm[k * 4 + 1];
        float e0 = (q1.x - q0.z) * (py - q0.w) - (q1.y - q0.w) * (px - q0.z);
        float e1 = (q0.x - q1.x) * (py - q1.y) - (q0.y - q1.y) * (px - q1.x);
        float b0 = e0 * q1.z;          // sign-exact vs e0/areaS
        float b1 = e1 * q1.z;
        if (b0 >= 0.0f && b1 >= 0.0f) {
            float b2 = 1.0f - b0 - b1;
            bool inside;
            if (b2 > TAU)       inside = true;
            else if (b2 < -TAU) inside = false;
            else {             // boundary band: replicate reference divisions exactly
                float bb0 = e0 / q1.w;
                float bb1 = e1 / q1.w;
                inside = (1.0f - bb0 - bb1) >= 0.0f;
                b0 = bb0; b1 = bb1;
            }
            if (inside) {
                float b2e = 1.0f - b0 - b1;
                float S = b0 * q2.x + b1 * q2.y + b2e * q2.z;
                if (S > bestS) {
                    float d = 1.0f / fmaxf(S, EPSV);     // exact, only on updates
                    if (d < bestd) { bestd = d; bestS = S; bestf = fbeg + k; }
                }
            }
        }
    }

    if (bestf >= 0) {
        unsigned long long key =
            ~(((unsigned long long)__float_as_uint(bestd) << 32) | (unsigned)bestf);
        atomicMax(&g_best[b][pix], key);
    }

    // ---- last-block-per-tile shading ----
    __threadfence();                 // make this thread's commit visible
    __syncthreads();
    if (tid == 0) sOld = atomicAdd(&g_tilecnt[b][blockIdx.x], 1);
    __syncthreads();
    if (sOld != NSPLIT - 1) return;  // not the last chunk-block for this tile
    __threadfence();                 // acquire: all tile commits visible

    unsigned long long key = g_best[b][pix];
    g_best[b][pix] = 0ull;           // self-reset for next replay
    if (tid == 0) g_tilecnt[b][blockIdx.x] = 0;
    bool hit = (key != 0ull);
    float r = 1.0f, g = 1.0f, bl = 1.0f;
    if (hit) {
        int wf = (int)((~key) & 0xFFFFFFFFull);
        int i0 = faces[wf * 3 + 0];
        int i1 = faces[wf * 3 + 1];
        int i2 = faces[wf * 3 + 2];
        float a0x = g_vtx[b][i0][0], a0y = g_vtx[b][i0][1], t0 = g_vtx[b][i0][2];
        float a1x = g_vtx[b][i1][0], a1y = g_vtx[b][i1][1], t1 = g_vtx[b][i1][2];
        float a2x = g_vtx[b][i2][0], a2y = g_vtx[b][i2][1], t2 = g_vtx[b][i2][2];
        float ar = (a1x - a0x) * (a2y - a0y) - (a1y - a0y) * (a2x - a0x);
        if (fabsf(ar) < EPSV) ar = EPSV;
        float iar = __fdividef(1.0f, ar);
        float bb0 = ((a2x - a1x) * (py - a1y) - (a2y - a1y) * (px - a1x)) * iar;
        float bb1 = ((a0x - a2x) * (py - a2y) - (a0y - a2y) * (px - a2x)) * iar;
        float bb2 = 1.0f - bb0 - bb1;
        float w0 = __fdividef(bb0, t0), w1 = __fdividef(bb1, t1), w2 = __fdividef(bb2, t2);
        float is = __fdividef(1.0f, w0 + w1 + w2 + EPSV);
        float p0 = w0 * is, p1 = w1 * is, p2 = w2 * is;

        const float* wv0 = &verts[(b * NV + i0) * 3];
        const float* wv1 = &verts[(b * NV + i1) * 3];
        const float* wv2 = &verts[(b * NV + i2) * 3];
        float posx = p0 * wv0[0] + p1 * wv1[0] + p2 * wv2[0];
        float posy = p0 * wv0[1] + p1 * wv1[1] + p2 * wv2[1];
        float posz = p0 * wv0[2] + p1 * wv1[2] + p2 * wv2[2];

        float n0x = g_vn[b][i0][0], n0y = g_vn[b][i0][1], n0z = g_vn[b][i0][2];
        float n1x = g_vn[b][i1][0], n1y = g_vn[b][i1][1], n1z = g_vn[b][i1][2];
        float n2x = g_vn[b][i2][0], n2y = g_vn[b][i2][1], n2z = g_vn[b][i2][2];
        float r0 = __fdividef(1.0f, sqrtf(n0x * n0x + n0y * n0y + n0z * n0z) + EPSV);
        float r1 = __fdividef(1.0f, sqrtf(n1x * n1x + n1y * n1y + n1z * n1z) + EPSV);
        float r2 = __fdividef(1.0f, sqrtf(n2x * n2x + n2y * n2y + n2z * n2z) + EPSV);
        float nx = p0 * n0x * r0 + p1 * n1x * r1 + p2 * n2x * r2;
        float ny = p0 * n0y * r0 + p1 * n1y * r1 + p2 * n2y * r2;
        float nz = p0 * n0z * r0 + p1 * n1z * r1 + p2 * n2z * r2;
        float rn = __fdividef(1.0f, sqrtf(nx * nx + ny * ny + nz * nz) + EPSV);
        nx *= rn; ny *= rn; nz *= rn;

        float lx = 0.0f - posx, ly = 1.0f - posy, lz = 3.0f - posz;
        float rl = __fdividef(1.0f, sqrtf(lx * lx + ly * ly + lz * lz) + EPSV);
        lx *= rl; ly *= rl; lz *= rl;
        float vx = 0.0f - posx, vy = 0.0f - posy, vz = 2.0f - posz;
        float rv = __fdividef(1.0f, sqrtf(vx * vx + vy * vy + vz * vz) + EPSV);
        vx *= rv; vy *= rv; vz *= rv;

        float dnl = nx * lx + ny * ly + nz * lz;
        float ndl = fmaxf(dnl, 0.0f);
        float rx = 2.0f * dnl * nx - lx;
        float ry = 2.0f * dnl * ny - ly;
        float rz = 2.0f * dnl * nz - lz;
        float sc = fmaxf(rx * vx + ry * vy + rz * vz, 0.0f);
        float s2 = sc * sc, s4 = s2 * s2, s8 = s4 * s4;
        float spec = 0.2f * 0.6f * (s8 * s2);
        float shade = 0.5f + 0.3f * ndl;
        r  = (142.0f / 255.0f) * shade + spec;
        g  = (179.0f / 255.0f) * shade + spec;
        bl = (247.0f / 255.0f) * shade + spec;
    }
    int plane = IH * IW;
    out[(b * 3 + 0) * plane + pix] = r * 255.0f;
    out[(b * 3 + 1) * plane + pix] = g * 255.0f;
    out[(b * 3 + 2) * plane + pix] = bl * 255.0f;
    out[NB * 3 * plane + b * plane + pix] = hit ? 1.0f : 0.0f;

    // ---- global tail: last shading block re-zeroes g_vn for next replay ----
    __threadfence();
    __syncthreads();
    if (tid == 0) sOld = atomicAdd(&g_shadecnt, 1);
    __syncthreads();
    if (sOld == NB * 64 - 1) {
        float* vn = (float*)g_vn;
        for (int t = tid; t < NB * NV * 3; t += 256) vn[t] = 0.0f;
        if (tid == 0) g_shadecnt = 0;
    }
}

extern "C" void kernel_launch(void* const* d_in, const int* in_sizes, int n_in,
                              void* d_out, int out_size) {
    const float* verts = (const float*)d_in[0];
    const int* faces = (const int*)d_in[1];
    float* out = (float*)d_out;

    k_prep<<<(NB * NF + 255) / 256, 256>>>(verts, faces);
    dim3 grid(64, NB, NSPLIT);
    k_render<<<grid, 256>>>(verts, faces, out);
}

// round 8
// speedup vs baseline: 1.1867x; 1.1867x over previous
#include <cuda_runtime.h>
#include <math.h>

#define NB 2
#define NV 1300
#define NF 2500
#define IH 128
#define IW 128
#define EPSV 1e-8f
#define NSPLIT 32
#define CHMAX 80    // ceil(2500/32)=79, rounded
#define TAU 1e-4f

// Scratch (allocation-free rule: __device__ globals; zero-initialized at load)
__device__ float  g_vtx[NB][NV][3];             // ndcx, ndcy, viewz
__device__ float  g_vn[NB][NV][3];              // accumulated vertex normals
__device__ float  g_fn[NB][NF][3];              // per-face world normals
__device__ float4 g_fd[NB][NF * 4];             // per-face packed raster data
// inverted keys: 0 = empty. key = ~((depthbits<<32)|face). atomicMax == min over (depth,face).
__device__ unsigned long long g_best[NB][IH * IW];

__device__ __noinline__ float3 xform(float x, float y, float z) {
    float vz = 2.0f - z;                 // view = verts @ diag(-1,1,-1) + (0,0,2)
    float nx = 12.0f * (-x) / vz;
    float ny = 12.0f * y / vz;
    return make_float3(nx, ny, vz);
}

// Fused prep: vertex transform + vn zero + face raster data + face normals
__global__ void k_prep(const float* __restrict__ verts, const int* __restrict__ faces) {
    int idx = blockIdx.x * blockDim.x + threadIdx.x;
    if (idx < NB * NV) {
        int b = idx / NV, v = idx - b * NV;
        float3 t = xform(verts[idx * 3 + 0], verts[idx * 3 + 1], verts[idx * 3 + 2]);
        g_vtx[b][v][0] = t.x;
        g_vtx[b][v][1] = t.y;
        g_vtx[b][v][2] = t.z;
        g_vn[b][v][0] = 0.0f; g_vn[b][v][1] = 0.0f; g_vn[b][v][2] = 0.0f;
    }
    if (idx < NB * NF) {
        int b = idx / NF, f = idx - b * NF;
        int i0 = faces[f * 3 + 0];
        int i1 = faces[f * 3 + 1];
        int i2 = faces[f * 3 + 2];
        const float* w0 = &verts[(b * NV + i0) * 3];
        const float* w1 = &verts[(b * NV + i1) * 3];
        const float* w2 = &verts[(b * NV + i2) * 3];
        float w0x = w0[0], w0y = w0[1], w0z = w0[2];
        float w1x = w1[0], w1y = w1[1], w1z = w1[2];
        float w2x = w2[0], w2y = w2[1], w2z = w2[2];
        float ax = w1x - w0x, ay = w1y - w0y, az = w1z - w0z;
        float bx = w2x - w0x, by = w2y - w0y, bz = w2z - w0z;
        g_fn[b][f][0] = ay * bz - az * by;
        g_fn[b][f][1] = az * bx - ax * bz;
        g_fn[b][f][2] = ax * by - ay * bx;

        float3 p0 = xform(w0x, w0y, w0z);
        float3 p1 = xform(w1x, w1y, w1z);
        float3 p2 = xform(w2x, w2y, w2z);
        float v0x = p0.x, v0y = p0.y, t0 = p0.z;
        float v1x = p1.x, v1y = p1.y, t1 = p1.z;
        float v2x = p2.x, v2y = p2.y, t2 = p2.z;

        float area = (v1x - v0x) * (v2y - v0y) - (v1y - v0y) * (v2x - v0x);
        float areaS = (fabsf(area) < EPSV) ? EPSV : area;
        float invA  = 1.0f / areaS;
        bool  ok    = fabsf(area) > EPSV;
        float pad = 1e-5f;
        float xmn = fminf(v0x, fminf(v1x, v2x)) - pad;
        float xmx = fmaxf(v0x, fmaxf(v1x, v2x)) + pad;
        float ymn = fminf(v0y, fminf(v1y, v2y)) - pad;
        float ymx = fmaxf(v0y, fmaxf(v1y, v2y)) + pad;
        if (!ok) { xmn = 1e30f; xmx = -1e30f; }   // degenerate: empty bbox
        g_fd[b][f * 4 + 0] = make_float4(v0x, v0y, v1x, v1y);
        g_fd[b][f * 4 + 1] = make_float4(v2x, v2y, invA, areaS);
        g_fd[b][f * 4 + 2] = make_float4(1.0f / t0, 1.0f / t1, 1.0f / t2, 0.0f);
        g_fd[b][f * 4 + 3] = make_float4(xmn, xmx, ymn, ymx);
    }
}

__global__ void __launch_bounds__(256) k_render(const int* __restrict__ faces) {
    int tid = threadIdx.x;

    // z-slice NSPLIT: vertex-normal atomic accumulation (independent work)
    if (blockIdx.z == NSPLIT) {
        int lid = blockIdx.y * gridDim.x + blockIdx.x;
        int idx = lid * 256 + tid;
        if (idx < NB * NF) {
            int b = idx / NF, f = idx - b * NF;
            float fx = g_fn[b][f][0], fy = g_fn[b][f][1], fz = g_fn[b][f][2];
            int i0 = faces[f * 3 + 0];
            int i1 = faces[f * 3 + 1];
            int i2 = faces[f * 3 + 2];
            atomicAdd(&g_vn[b][i0][0], fx); atomicAdd(&g_vn[b][i0][1], fy); atomicAdd(&g_vn[b][i0][2], fz);
            atomicAdd(&g_vn[b][i1][0], fx); atomicAdd(&g_vn[b][i1][1], fy); atomicAdd(&g_vn[b][i1][2], fz);
            atomicAdd(&g_vn[b][i2][0], fx); atomicAdd(&g_vn[b][i2][1], fy); atomicAdd(&g_vn[b][i2][2], fz);
        }
        return;
    }

    __shared__ float4 sm[CHMAX * 4];
    __shared__ unsigned short list[CHMAX];
    __shared__ int warpcnt[8];
    __shared__ int warpoff[8];
    __shared__ int nlist;

    int b = blockIdx.y;
    int chunk = blockIdx.z;
    int warp = tid >> 5, lane = tid & 31;
    int jx0 = (blockIdx.x & 7) << 4;
    int iy0 = (blockIdx.x >> 3) << 4;
    int j = jx0 + (tid & 15);
    int i = iy0 + (tid >> 4);
    float px = 1.0f - (2.0f * (float)j + 1.0f) * (1.0f / (float)IW);
    float py = 1.0f - (2.0f * (float)i + 1.0f) * (1.0f / (float)IH);
    float tpx_hi = 1.0f - (2.0f * (float)jx0 + 1.0f) * (1.0f / (float)IW);
    float tpx_lo = 1.0f - (2.0f * (float)(jx0 + 15) + 1.0f) * (1.0f / (float)IW);
    float tpy_hi = 1.0f - (2.0f * (float)iy0 + 1.0f) * (1.0f / (float)IH);
    float tpy_lo = 1.0f - (2.0f * (float)(iy0 + 15) + 1.0f) * (1.0f / (float)IH);

    const int CH = (NF + NSPLIT - 1) / NSPLIT;       // 79
    int fbeg = chunk * CH;
    int cnt = min(NF, fbeg + CH) - fbeg;

    const float4* fd = g_fd[b];
    for (int k = tid; k < cnt * 4; k += 256) sm[k] = fd[fbeg * 4 + k];
    if (tid == 0) nlist = 0;
    __syncthreads();

    // Order-preserving compaction: faces whose bbox intersects the tile rect.
    {
        int k = tid;                      // CH=79 <= 256: single pass
        bool keep = false;
        if (k < cnt) {
            float4 bb = sm[k * 4 + 3];
            keep = (bb.x <= tpx_hi) & (bb.y >= tpx_lo) & (bb.z <= tpy_hi) & (bb.w >= tpy_lo);
        }
        unsigned m = __ballot_sync(0xffffffffu, keep);
        if (lane == 0) warpcnt[warp] = __popc(m);
        __syncthreads();
        if (tid == 0) {
            int s = 0;
            #pragma unroll
            for (int w = 0; w < 8; w++) { warpoff[w] = s; s += warpcnt[w]; }
            nlist = s;
        }
        __syncthreads();
        if (keep) {
            int pos = warpoff[warp] + __popc(m & ((1u << lane) - 1u));
            list[pos] = (unsigned short)k;
        }
        __syncthreads();
    }
    int nl = nlist;

    // NO early-z, NO snapshot — straight R3-style loop (correctness bisection).
    float bestd = __int_as_float(0x7f800000);
    float bestS = EPSV;
    int bestf = -1;

    for (int t = 0; t < nl; t++) {
        int k = (int)list[t];
        float4 bb = sm[k * 4 + 3];
        if (px < bb.x || px > bb.y || py < bb.z || py > bb.w) continue;
        float4 q0 = sm[k * 4 + 0];
        float4 q1 = sm[k * 4 + 1];
        float e0 = (q1.x - q0.z) * (py - q0.w) - (q1.y - q0.w) * (px - q0.z);
        float e1 = (q0.x - q1.x) * (py - q1.y) - (q0.y - q1.y) * (px - q1.x);
        float b0 = e0 * q1.z;          // sign-exact vs e0/areaS
        float b1 = e1 * q1.z;
        if (b0 >= 0.0f && b1 >= 0.0f) {
            float b2 = 1.0f - b0 - b1;
            bool inside;
            if (b2 > TAU)       inside = true;
            else if (b2 < -TAU) inside = false;
            else {             // boundary band: replicate reference divisions exactly
                float bb0 = e0 / q1.w;
                float bb1 = e1 / q1.w;
                inside = (1.0f - bb0 - bb1) >= 0.0f;
                b0 = bb0; b1 = bb1;
            }
            if (inside) {
                float4 q2 = sm[k * 4 + 2];     // loaded only for survivors
                float b2e = 1.0f - b0 - b1;
                float S = b0 * q2.x + b1 * q2.y + b2e * q2.z;
                if (S > bestS) {
                    float d = 1.0f / fmaxf(S, EPSV);     // exact, only on updates
                    if (d < bestd) { bestd = d; bestS = S; bestf = fbeg + k; }
                }
            }
        }
    }

    if (bestf >= 0) {
        unsigned long long key =
            ~(((unsigned long long)__float_as_uint(bestd) << 32) | (unsigned)bestf);
        atomicMax(&g_best[b][i * IW + j], key);
    }
}

__global__ void k_shade(const float* __restrict__ verts, const int* __restrict__ faces,
                        float* __restrict__ out) {
    int idx = blockIdx.x * blockDim.x + threadIdx.x;
    if (idx >= NB * IH * IW) return;
    int b = idx / (IH * IW);
    int pix = idx - b * (IH * IW);
    int i = pix / IW, j = pix - i * IW;
    float px = 1.0f - (2.0f * (float)j + 1.0f) * (1.0f / (float)IW);
    float py = 1.0f - (2.0f * (float)i + 1.0f) * (1.0f / (float)IH);

    unsigned long long key = g_best[b][pix];
    g_best[b][pix] = 0ull;                 // self-reset for next replay (own entry only)
    bool hit = (key != 0ull);
    float r = 1.0f, g = 1.0f, bl = 1.0f;
    if (hit) {
        int bestf = (int)((~key) & 0xFFFFFFFFull);
        int i0 = faces[bestf * 3 + 0];
        int i1 = faces[bestf * 3 + 1];
        int i2 = faces[bestf * 3 + 2];
        float a0x = g_vtx[b][i0][0], a0y = g_vtx[b][i0][1], t0 = g_vtx[b][i0][2];
        float a1x = g_vtx[b][i1][0], a1y = g_vtx[b][i1][1], t1 = g_vtx[b][i1][2];
        float a2x = g_vtx[b][i2][0], a2y = g_vtx[b][i2][1], t2 = g_vtx[b][i2][2];
        float ar = (a1x - a0x) * (a2y - a0y) - (a1y - a0y) * (a2x - a0x);
        if (fabsf(ar) < EPSV) ar = EPSV;
        // exact IEEE divisions (R3-identical shade math)
        float bb0 = ((a2x - a1x) * (py - a1y) - (a2y - a1y) * (px - a1x)) / ar;
        float bb1 = ((a0x - a2x) * (py - a2y) - (a0y - a2y) * (px - a2x)) / ar;
        float bb2 = 1.0f - bb0 - bb1;
        float w0 = bb0 / t0, w1 = bb1 / t1, w2 = bb2 / t2;
        float s = w0 + w1 + w2 + EPSV;
        float p0 = w0 / s, p1 = w1 / s, p2 = w2 / s;

        const float* wv0 = &verts[(b * NV + i0) * 3];
        const float* wv1 = &verts[(b * NV + i1) * 3];
        const float* wv2 = &verts[(b * NV + i2) * 3];
        float posx = p0 * wv0[0] + p1 * wv1[0] + p2 * wv2[0];
        float posy = p0 * wv0[1] + p1 * wv1[1] + p2 * wv2[1];
        float posz = p0 * wv0[2] + p1 * wv1[2] + p2 * wv2[2];

        float n0x = g_vn[b][i0][0], n0y = g_vn[b][i0][1], n0z = g_vn[b][i0][2];
        float n1x = g_vn[b][i1][0], n1y = g_vn[b][i1][1], n1z = g_vn[b][i1][2];
        float n2x = g_vn[b][i2][0], n2y = g_vn[b][i2][1], n2z = g_vn[b][i2][2];
        float n0 = sqrtf(n0x * n0x + n0y * n0y + n0z * n0z) + EPSV;
        float n1 = sqrtf(n1x * n1x + n1y * n1y + n1z * n1z) + EPSV;
        float n2 = sqrtf(n2x * n2x + n2y * n2y + n2z * n2z) + EPSV;
        n0x /= n0; n0y /= n0; n0z /= n0;
        n1x /= n1; n1y /= n1; n1z /= n1;
        n2x /= n2; n2y /= n2; n2z /= n2;

        float nx = p0 * n0x + p1 * n1x + p2 * n2x;
        float ny = p0 * n0y + p1 * n1y + p2 * n2y;
        float nz = p0 * n0z + p1 * n1z + p2 * n2z;
        float nn = sqrtf(nx * nx + ny * ny + nz * nz) + EPSV;
        nx /= nn; ny /= nn; nz /= nn;

        float lx = 0.0f - posx, ly = 1.0f - posy, lz = 3.0f - posz;
        float ln = sqrtf(lx * lx + ly * ly + lz * lz) + EPSV;
        lx /= ln; ly /= ln; lz /= ln;
        float vx = 0.0f - posx, vy = 0.0f - posy, vz = 2.0f - posz;
        float vnm = sqrtf(vx * vx + vy * vy + vz * vz) + EPSV;
        vx /= vnm; vy /= vnm; vz /= vnm;

        float dnl = nx * lx + ny * ly + nz * lz;
        float ndl = fmaxf(dnl, 0.0f);
        float rx = 2.0f * dnl * nx - lx;
        float ry = 2.0f * dnl * ny - ly;
        float rz = 2.0f * dnl * nz - lz;
        float sc = fmaxf(rx * vx + ry * vy + rz * vz, 0.0f);
        float s2 = sc * sc, s4 = s2 * s2, s8 = s4 * s4;
        float spec = 0.2f * 0.6f * (s8 * s2);
        float shade = 0.5f + 0.3f * ndl;
        r  = (142.0f / 255.0f) * shade + spec;
        g  = (179.0f / 255.0f) * shade + spec;
        bl = (247.0f / 255.0f) * shade + spec;
    }
    int plane = IH * IW;
    out[(b * 3 + 0) * plane + pix] = r * 255.0f;
    out[(b * 3 + 1) * plane + pix] = g * 255.0f;
    out[(b * 3 + 2) * plane + pix] = bl * 255.0f;
    out[NB * 3 * plane + b * plane + pix] = hit ? 1.0f : 0.0f;
}

extern "C" void kernel_launch(void* const* d_in, const int* in_sizes, int n_in,
                              void* d_out, int out_size) {
    const float* verts = (const float*)d_in[0];
    const int* faces = (const int*)d_in[1];
    float* out = (float*)d_out;

    k_prep<<<(NB * NF + 255) / 256, 256>>>(verts, faces);
    dim3 grid(64, NB, NSPLIT + 1);
    k_render<<<grid, 256>>>(faces);
    k_shade<<<(NB * IH * IW + 255) / 256, 256>>>(verts, faces, out);
}